// round 1
// baseline (speedup 1.0000x reference)
#include <cuda_runtime.h>
#include <math.h>

// Problem constants
#define B_SZ   128
#define C_SZ   32
#define HW_SZ  144      // 12*12
#define Q_SZ   8        // in_caps
#define O_SZ   10       // out_ch
#define P_SZ   16       // out_caps
#define BDIM   512

// SMEM layout (floats)
//   u_s  [32][144][8]    = 36864   (copy of x[b], same layout)
//   Wv   [2][32][10][8]  = 5120    (W contracted with v0 / v1)
//   S_s  [32][10][8]     = 2560    (per-c partial s contributions; iter0 uses [32][8])
//   s_b  [10][16]        = 160
//   v_b  [2][10][16]     = 320
//   sc_b [16]            = 16      (squash scales)
#define U_OFF   0
#define WV_OFF  36864
#define S_OFF   (WV_OFF + 5120)
#define SB_OFF  (S_OFF + 2560)
#define VB_OFF  (SB_OFF + 160)
#define SC_OFF  (VB_OFF + 320)
#define SMEM_FLOATS (SC_OFF + 16)
#define SMEM_BYTES  (SMEM_FLOATS * 4)

// ---------------------------------------------------------------------------
// One routing pass (iterations 1 and 2). NWV = number of Wv sets contributing
// to the logits b_ij (b is recomputed from v-history instead of stored).
// Each 16-lane group owns one c; lanes cover 144 spatial positions in 9 steps.
// Produces S_s[c][o][q] in shared memory.
// ---------------------------------------------------------------------------
template <int NWV>
__device__ __forceinline__ void route_pass(const float* __restrict__ u_s,
                                           const float* __restrict__ Wv,
                                           float* __restrict__ S_s,
                                           int c, int l16)
{
    float Sp[80];
#pragma unroll
    for (int z = 0; z < 80; ++z) Sp[z] = 0.f;

    const float4* wv0 = reinterpret_cast<const float4*>(Wv + c * 80);
    const float4* wv1 = reinterpret_cast<const float4*>(Wv + 2560 + c * 80);

#pragma unroll 1
    for (int j = 0; j < 9; ++j) {
        const int hw = j * 16 + l16;
        const float4* up =
            reinterpret_cast<const float4*>(u_s + c * (HW_SZ * Q_SZ) + hw * Q_SZ);
        const float4 u0 = up[0];
        const float4 u1 = up[1];

        float bb[10];
#pragma unroll
        for (int o = 0; o < 10; ++o) {
            float4 w0 = wv0[o * 2];
            float4 w1 = wv0[o * 2 + 1];
            float t = u0.x * w0.x + u0.y * w0.y + u0.z * w0.z + u0.w * w0.w
                    + u1.x * w1.x + u1.y * w1.y + u1.z * w1.z + u1.w * w1.w;
            if (NWV == 2) {
                float4 x0 = wv1[o * 2];
                float4 x1 = wv1[o * 2 + 1];
                t += u0.x * x0.x + u0.y * x0.y + u0.z * x0.z + u0.w * x0.w
                   + u1.x * x1.x + u1.y * x1.y + u1.z * x1.z + u1.w * x1.w;
            }
            bb[o] = t;
        }

        // softmax over o (max-subtracted)
        float m = bb[0];
#pragma unroll
        for (int o = 1; o < 10; ++o) m = fmaxf(m, bb[o]);
        float ssum = 0.f;
#pragma unroll
        for (int o = 0; o < 10; ++o) { bb[o] = __expf(bb[o] - m); ssum += bb[o]; }
        const float r = __fdividef(1.f, ssum);

        // S[c][o][q] += c_coef[o] * u[q]
#pragma unroll
        for (int o = 0; o < 10; ++o) {
            const float ce = bb[o] * r;
            Sp[o * 8 + 0] += ce * u0.x;
            Sp[o * 8 + 1] += ce * u0.y;
            Sp[o * 8 + 2] += ce * u0.z;
            Sp[o * 8 + 3] += ce * u0.w;
            Sp[o * 8 + 4] += ce * u1.x;
            Sp[o * 8 + 5] += ce * u1.y;
            Sp[o * 8 + 6] += ce * u1.z;
            Sp[o * 8 + 7] += ce * u1.w;
        }
    }

    // reduce the 16 lanes of this c-group
#pragma unroll
    for (int z = 0; z < 80; ++z) {
        float v = Sp[z];
        v += __shfl_xor_sync(0xffffffffu, v, 1);
        v += __shfl_xor_sync(0xffffffffu, v, 2);
        v += __shfl_xor_sync(0xffffffffu, v, 4);
        v += __shfl_xor_sync(0xffffffffu, v, 8);
        Sp[z] = v;
    }
    if (l16 == 0) {
#pragma unroll
        for (int z = 0; z < 80; ++z) S_s[c * 80 + z] = Sp[z];
    }
}

// s[o][p] = sum_{c,q} W[c,o,p,q] * S_s[c][o][q]    (threads 0..159)
__device__ __forceinline__ void contract_s_full(const float* __restrict__ Wg,
                                                const float* __restrict__ S_s,
                                                float* __restrict__ s_b, int tid)
{
    if (tid < 160) {
        const int o = tid >> 4, p = tid & 15;
        float acc = 0.f;
#pragma unroll 4
        for (int cc = 0; cc < 32; ++cc) {
            const float4* wp =
                reinterpret_cast<const float4*>(Wg + cc * 1280 + o * 128 + p * 8);
            const float4* sp = reinterpret_cast<const float4*>(S_s + cc * 80 + o * 8);
            float4 w0 = wp[0], w1 = wp[1], a0 = sp[0], a1 = sp[1];
            acc += w0.x * a0.x + w0.y * a0.y + w0.z * a0.z + w0.w * a0.w
                 + w1.x * a1.x + w1.y * a1.y + w1.z * a1.z + w1.w * a1.w;
        }
        s_b[tid] = acc;
    }
}

// squash scales: sc[o] = sqrt(sn)/(1+sn)
__device__ __forceinline__ void squash_scales(const float* __restrict__ s_b,
                                              float* __restrict__ sc_b, int tid)
{
    if (tid < 10) {
        float sn = 0.f;
#pragma unroll
        for (int p = 0; p < 16; ++p) { float t = s_b[tid * 16 + p]; sn += t * t; }
        sc_b[tid] = sqrtf(sn) / (1.f + sn);
    }
}

// Wv[set][c][o][q] = sum_p W[c,o,p,q] * v[o][p]    (threads 0..319)
__device__ __forceinline__ void compute_Wv(const float* __restrict__ Wg,
                                           const float* __restrict__ vrow_base,
                                           float* __restrict__ Wv_set, int tid)
{
    if (tid < 320) {
        const int cc = tid / 10;
        const int o  = tid - cc * 10;
        const float* wrow = Wg + cc * 1280 + o * 128;
        const float* vrow = vrow_base + o * 16;
        float acc[8];
#pragma unroll
        for (int q = 0; q < 8; ++q) acc[q] = 0.f;
#pragma unroll
        for (int p = 0; p < 16; ++p) {
            const float vp = vrow[p];
            const float4* wp = reinterpret_cast<const float4*>(wrow + p * 8);
            float4 w0 = wp[0], w1 = wp[1];
            acc[0] += w0.x * vp; acc[1] += w0.y * vp;
            acc[2] += w0.z * vp; acc[3] += w0.w * vp;
            acc[4] += w1.x * vp; acc[5] += w1.y * vp;
            acc[6] += w1.z * vp; acc[7] += w1.w * vp;
        }
        float4* dst = reinterpret_cast<float4*>(Wv_set + cc * 80 + o * 8);
        dst[0] = make_float4(acc[0], acc[1], acc[2], acc[3]);
        dst[1] = make_float4(acc[4], acc[5], acc[6], acc[7]);
    }
}

__global__ __launch_bounds__(BDIM, 1)
void caps_routing_kernel(const float* __restrict__ xg,
                         const float* __restrict__ Wg,
                         float* __restrict__ outg)
{
    extern __shared__ float sm[];
    float* u_s  = sm + U_OFF;
    float* Wv   = sm + WV_OFF;
    float* S_s  = sm + S_OFF;
    float* s_b  = sm + SB_OFF;
    float* v_b  = sm + VB_OFF;
    float* sc_b = sm + SC_OFF;

    const int b   = blockIdx.x;
    const int tid = threadIdx.x;

    // ---- load x[b] (layout [c][hw][q] is identical to gmem) ----
    {
        const float4* src = reinterpret_cast<const float4*>(xg + (size_t)b * 36864);
        float4* dst = reinterpret_cast<float4*>(u_s);
#pragma unroll
        for (int i = 0; i < 18; ++i) dst[tid + i * BDIM] = src[tid + i * BDIM];
    }
    __syncthreads();

    const int lane = tid & 31;
    const int l16  = lane & 15;
    const int c    = (tid >> 5) * 2 + (lane >> 4);

    // ======================= iteration 0 (c_ij = 1/10) =======================
    {
        float S0[8];
#pragma unroll
        for (int q = 0; q < 8; ++q) S0[q] = 0.f;
#pragma unroll
        for (int j = 0; j < 9; ++j) {
            const float4* up = reinterpret_cast<const float4*>(
                u_s + c * (HW_SZ * Q_SZ) + (j * 16 + l16) * Q_SZ);
            float4 a = up[0], bq = up[1];
            S0[0] += a.x;  S0[1] += a.y;  S0[2] += a.z;  S0[3] += a.w;
            S0[4] += bq.x; S0[5] += bq.y; S0[6] += bq.z; S0[7] += bq.w;
        }
#pragma unroll
        for (int q = 0; q < 8; ++q) {
            S0[q] += __shfl_xor_sync(0xffffffffu, S0[q], 1);
            S0[q] += __shfl_xor_sync(0xffffffffu, S0[q], 2);
            S0[q] += __shfl_xor_sync(0xffffffffu, S0[q], 4);
            S0[q] += __shfl_xor_sync(0xffffffffu, S0[q], 8);
        }
        if (l16 == 0) {
#pragma unroll
            for (int q = 0; q < 8; ++q) S_s[c * 8 + q] = S0[q] * 0.1f;
        }
    }
    __syncthreads();

    // s0[o][p] = sum_{c,q} W[c,o,p,q] * S_s[c][q]
    if (tid < 160) {
        const int o = tid >> 4, p = tid & 15;
        float acc = 0.f;
#pragma unroll 4
        for (int cc = 0; cc < 32; ++cc) {
            const float4* wp =
                reinterpret_cast<const float4*>(Wg + cc * 1280 + o * 128 + p * 8);
            const float4* sp = reinterpret_cast<const float4*>(S_s + cc * 8);
            float4 w0 = wp[0], w1 = wp[1], a0 = sp[0], a1 = sp[1];
            acc += w0.x * a0.x + w0.y * a0.y + w0.z * a0.z + w0.w * a0.w
                 + w1.x * a1.x + w1.y * a1.y + w1.z * a1.z + w1.w * a1.w;
        }
        s_b[tid] = acc;
    }
    __syncthreads();
    squash_scales(s_b, sc_b, tid);
    __syncthreads();
    if (tid < 160) v_b[tid] = s_b[tid] * sc_b[tid >> 4];   // v0
    __syncthreads();
    compute_Wv(Wg, v_b, Wv, tid);                          // Wv set 0
    __syncthreads();

    // ======================= iteration 1 =======================
    route_pass<1>(u_s, Wv, S_s, c, l16);
    __syncthreads();
    contract_s_full(Wg, S_s, s_b, tid);
    __syncthreads();
    squash_scales(s_b, sc_b, tid);
    __syncthreads();
    if (tid < 160) v_b[160 + tid] = s_b[tid] * sc_b[tid >> 4];   // v1
    __syncthreads();
    compute_Wv(Wg, v_b + 160, Wv + 2560, tid);                   // Wv set 1
    __syncthreads();

    // ======================= iteration 2 =======================
    route_pass<2>(u_s, Wv, S_s, c, l16);
    __syncthreads();
    contract_s_full(Wg, S_s, s_b, tid);
    __syncthreads();
    squash_scales(s_b, sc_b, tid);
    __syncthreads();
    if (tid < 160) outg[b * 160 + tid] = s_b[tid] * sc_b[tid >> 4];  // v2 -> out
}

extern "C" void kernel_launch(void* const* d_in, const int* in_sizes, int n_in,
                              void* d_out, int out_size)
{
    const float* x = (const float*)d_in[0];
    const float* W = (const float*)d_in[1];
    // defensive: x has 4,718,592 elems, W has 40,960 — swap if order differs
    if (n_in >= 2 && in_sizes[0] < in_sizes[1]) {
        const float* t = x; x = W; W = t;
    }
    (void)out_size;

    cudaFuncSetAttribute(caps_routing_kernel,
                         cudaFuncAttributeMaxDynamicSharedMemorySize, SMEM_BYTES);
    caps_routing_kernel<<<B_SZ, BDIM, SMEM_BYTES>>>(x, W, (float*)d_out);
}

// round 2
// speedup vs baseline: 1.4642x; 1.4642x over previous
#include <cuda_runtime.h>
#include <math.h>

#define B_SZ   128
#define C_SZ   32
#define HW_SZ  144
#define Q_SZ   8
#define O_SZ   10
#define P_SZ   16
#define BDIM   512

// padded u stride per c: 144*8 = 1152 -> 1160 floats (shifts half-warp by 32B,
// kills the 2-way LDS bank conflict between the two c's of a warp)
#define U_STRIDE 1160

// SMEM layout (floats)
#define U_OFF   0
#define U_SIZE  (32 * U_STRIDE)          // 37120
#define WV_OFF  U_SIZE                    // accumulated Wv  [32][10][8] = 2560
#define S_OFF   (WV_OFF + 2560)           // S_s [32][10][8] = 2560 (iter0: [32][8])
#define SB_OFF  (S_OFF + 2560)            // s_b [10][16] = 160
#define SMEM_FLOATS (SB_OFF + 160)
#define SMEM_BYTES  (SMEM_FLOATS * 4)

// ---------------------------------------------------------------------------
// Split-butterfly reduction over the 16-lane group: reduces N values held in
// each lane into N total values distributed 16-wise (N/16 per lane), returning
// the base index this lane ends up owning. Shuffle count: N/2+N/4+N/8+N/16.
// ---------------------------------------------------------------------------
__device__ __forceinline__ int split_reduce80(float* v, int l16)
{
    int base = 0;
    {   // mask 1, half 40
        const bool up = (l16 & 1);
#pragma unroll
        for (int z = 0; z < 40; ++z) {
            float keep = up ? v[40 + z] : v[z];
            float give = up ? v[z] : v[40 + z];
            v[z] = keep + __shfl_xor_sync(0xffffffffu, give, 1);
        }
        if (up) base += 40;
    }
    {   // mask 2, half 20
        const bool up = (l16 & 2);
#pragma unroll
        for (int z = 0; z < 20; ++z) {
            float keep = up ? v[20 + z] : v[z];
            float give = up ? v[z] : v[20 + z];
            v[z] = keep + __shfl_xor_sync(0xffffffffu, give, 2);
        }
        if (up) base += 20;
    }
    {   // mask 4, half 10
        const bool up = (l16 & 4);
#pragma unroll
        for (int z = 0; z < 10; ++z) {
            float keep = up ? v[10 + z] : v[z];
            float give = up ? v[z] : v[10 + z];
            v[z] = keep + __shfl_xor_sync(0xffffffffu, give, 4);
        }
        if (up) base += 10;
    }
    {   // mask 8, half 5
        const bool up = (l16 & 8);
#pragma unroll
        for (int z = 0; z < 5; ++z) {
            float keep = up ? v[5 + z] : v[z];
            float give = up ? v[z] : v[5 + z];
            v[z] = keep + __shfl_xor_sync(0xffffffffu, give, 8);
        }
        if (up) base += 5;
    }
    return base;
}

// ---------------------------------------------------------------------------
// Routing pass (iterations 1 & 2). Wv is the ACCUMULATED sum of Wv(v_k) over
// all previous iterations, so the logit dot is always a single 8-FMA per o.
// 16 lanes per c; 9 spatial steps per lane. Writes S_s[c][o][q].
// ---------------------------------------------------------------------------
__device__ __forceinline__ void route_pass(const float* __restrict__ u_s,
                                           const float* __restrict__ Wv,
                                           float* __restrict__ S_s,
                                           int c, int l16)
{
    float Sp[80];
#pragma unroll
    for (int z = 0; z < 80; ++z) Sp[z] = 0.f;

    const float4* wv = reinterpret_cast<const float4*>(Wv + c * 80);
    const float* ubase = u_s + c * U_STRIDE;

#pragma unroll 1
    for (int j = 0; j < 9; ++j) {
        const float4* up =
            reinterpret_cast<const float4*>(ubase + (j * 16 + l16) * Q_SZ);
        const float4 u0 = up[0];
        const float4 u1 = up[1];

        float bb[10];
#pragma unroll
        for (int o = 0; o < 10; ++o) {
            float4 w0 = wv[o * 2];
            float4 w1 = wv[o * 2 + 1];
            bb[o] = u0.x * w0.x + u0.y * w0.y + u0.z * w0.z + u0.w * w0.w
                  + u1.x * w1.x + u1.y * w1.y + u1.z * w1.z + u1.w * w1.w;
        }

        float m = bb[0];
#pragma unroll
        for (int o = 1; o < 10; ++o) m = fmaxf(m, bb[o]);
        float ssum = 0.f;
#pragma unroll
        for (int o = 0; o < 10; ++o) { bb[o] = __expf(bb[o] - m); ssum += bb[o]; }
        const float r = __fdividef(1.f, ssum);

#pragma unroll
        for (int o = 0; o < 10; ++o) {
            const float ce = bb[o] * r;
            Sp[o * 8 + 0] += ce * u0.x;
            Sp[o * 8 + 1] += ce * u0.y;
            Sp[o * 8 + 2] += ce * u0.z;
            Sp[o * 8 + 3] += ce * u0.w;
            Sp[o * 8 + 4] += ce * u1.x;
            Sp[o * 8 + 5] += ce * u1.y;
            Sp[o * 8 + 6] += ce * u1.z;
            Sp[o * 8 + 7] += ce * u1.w;
        }
    }

    const int base = split_reduce80(Sp, l16);
#pragma unroll
    for (int z = 0; z < 5; ++z) S_s[c * 80 + base + z] = Sp[z];
}

// s[o][p] = sum_{c,q} W[c,o,p,q] * S_s[c][o][q]   (threads 0..159)
__device__ __forceinline__ void contract_s_full(const float* __restrict__ Wg,
                                                const float* __restrict__ S_s,
                                                float* __restrict__ s_b, int tid)
{
    if (tid < 160) {
        const int o = tid >> 4, p = tid & 15;
        float a0 = 0.f, a1 = 0.f, a2 = 0.f, a3 = 0.f;
#pragma unroll 4
        for (int cc = 0; cc < 32; ++cc) {
            const float4* wp =
                reinterpret_cast<const float4*>(Wg + cc * 1280 + o * 128 + p * 8);
            const float4* sp = reinterpret_cast<const float4*>(S_s + cc * 80 + o * 8);
            float4 w0 = wp[0], w1 = wp[1], b0 = sp[0], b1 = sp[1];
            a0 += w0.x * b0.x + w0.y * b0.y;
            a1 += w0.z * b0.z + w0.w * b0.w;
            a2 += w1.x * b1.x + w1.y * b1.y;
            a3 += w1.z * b1.z + w1.w * b1.w;
        }
        s_b[tid] = (a0 + a1) + (a2 + a3);
    }
}

// Wv[c][o][q] (+)= sum_p W[c,o,p,q] * v[o][p], with v = squash(s) computed
// inline from s_b.  threads 0..319 (one per (c,o)).
template <bool ACC>
__device__ __forceinline__ void compute_Wv(const float* __restrict__ Wg,
                                           const float* __restrict__ s_b,
                                           float* __restrict__ Wv, int tid)
{
    if (tid < 320) {
        const int cc = tid / 10;
        const int o  = tid - cc * 10;
        const float* srow = s_b + o * 16;
        float sv[16];
        float sn = 0.f;
#pragma unroll
        for (int p = 0; p < 16; ++p) { sv[p] = srow[p]; sn += sv[p] * sv[p]; }
        const float sc = __fdividef(__fsqrt_rn(sn), 1.f + sn);

        const float* wrow = Wg + cc * 1280 + o * 128;
        float acc[8];
#pragma unroll
        for (int q = 0; q < 8; ++q) acc[q] = 0.f;
#pragma unroll
        for (int p = 0; p < 16; ++p) {
            const float vp = sv[p] * sc;
            const float4* wp = reinterpret_cast<const float4*>(wrow + p * 8);
            float4 w0 = wp[0], w1 = wp[1];
            acc[0] += w0.x * vp; acc[1] += w0.y * vp;
            acc[2] += w0.z * vp; acc[3] += w0.w * vp;
            acc[4] += w1.x * vp; acc[5] += w1.y * vp;
            acc[6] += w1.z * vp; acc[7] += w1.w * vp;
        }
        float4* dst = reinterpret_cast<float4*>(Wv + cc * 80 + o * 8);
        if (ACC) {
            float4 o0 = dst[0], o1 = dst[1];
            dst[0] = make_float4(o0.x + acc[0], o0.y + acc[1], o0.z + acc[2], o0.w + acc[3]);
            dst[1] = make_float4(o1.x + acc[4], o1.y + acc[5], o1.z + acc[6], o1.w + acc[7]);
        } else {
            dst[0] = make_float4(acc[0], acc[1], acc[2], acc[3]);
            dst[1] = make_float4(acc[4], acc[5], acc[6], acc[7]);
        }
    }
}

__global__ __launch_bounds__(BDIM, 1)
void caps_routing_kernel(const float* __restrict__ xg,
                         const float* __restrict__ Wg,
                         float* __restrict__ outg)
{
    extern __shared__ float sm[];
    float* u_s = sm + U_OFF;
    float* Wv  = sm + WV_OFF;
    float* S_s = sm + S_OFF;
    float* s_b = sm + SB_OFF;

    const int b   = blockIdx.x;
    const int tid = threadIdx.x;

    // ---- load x[b] into padded SMEM layout [c][144][8], c-stride 1160 ----
    {
        const float4* src = reinterpret_cast<const float4*>(xg + (size_t)b * 36864);
        float4* dst = reinterpret_cast<float4*>(u_s);
#pragma unroll
        for (int k = 0; k < 18; ++k) {
            const int i = tid + k * BDIM;          // 0..9215 (288 float4 per c)
            const int cc = i / 288;
            dst[cc * 290 + (i - cc * 288)] = src[i];
        }
    }
    __syncthreads();

    const int lane = tid & 31;
    const int l16  = lane & 15;
    const int c    = (tid >> 5) * 2 + (lane >> 4);

    // ======================= iteration 0 (c_ij = 1/10) =======================
    {
        float S0[8];
#pragma unroll
        for (int q = 0; q < 8; ++q) S0[q] = 0.f;
        const float* ubase = u_s + c * U_STRIDE;
#pragma unroll
        for (int j = 0; j < 9; ++j) {
            const float4* up =
                reinterpret_cast<const float4*>(ubase + (j * 16 + l16) * Q_SZ);
            float4 a = up[0], bq = up[1];
            S0[0] += a.x;  S0[1] += a.y;  S0[2] += a.z;  S0[3] += a.w;
            S0[4] += bq.x; S0[5] += bq.y; S0[6] += bq.z; S0[7] += bq.w;
        }
        // split reduce 8 values over 16 lanes
        int base = 0;
        {
            const bool up = (l16 & 1);
#pragma unroll
            for (int z = 0; z < 4; ++z) {
                float keep = up ? S0[4 + z] : S0[z];
                float give = up ? S0[z] : S0[4 + z];
                S0[z] = keep + __shfl_xor_sync(0xffffffffu, give, 1);
            }
            if (up) base += 4;
        }
        {
            const bool up = (l16 & 2);
#pragma unroll
            for (int z = 0; z < 2; ++z) {
                float keep = up ? S0[2 + z] : S0[z];
                float give = up ? S0[z] : S0[2 + z];
                S0[z] = keep + __shfl_xor_sync(0xffffffffu, give, 2);
            }
            if (up) base += 2;
        }
        {
            const bool up = (l16 & 4);
            float keep = up ? S0[1] : S0[0];
            float give = up ? S0[0] : S0[1];
            S0[0] = keep + __shfl_xor_sync(0xffffffffu, give, 4);
            if (up) base += 1;
        }
        S0[0] += __shfl_xor_sync(0xffffffffu, S0[0], 8);
        if (l16 < 8) S_s[c * 8 + base] = S0[0] * 0.1f;
    }
    __syncthreads();

    // s0[o][p] = sum_{c,q} W[c,o,p,q] * S_s[c][q]
    if (tid < 160) {
        const int o = tid >> 4, p = tid & 15;
        float a0 = 0.f, a1 = 0.f;
#pragma unroll 4
        for (int cc = 0; cc < 32; ++cc) {
            const float4* wp =
                reinterpret_cast<const float4*>(Wg + cc * 1280 + o * 128 + p * 8);
            const float4* sp = reinterpret_cast<const float4*>(S_s + cc * 8);
            float4 w0 = wp[0], w1 = wp[1], b0 = sp[0], b1 = sp[1];
            a0 += w0.x * b0.x + w0.y * b0.y + w0.z * b0.z + w0.w * b0.w;
            a1 += w1.x * b1.x + w1.y * b1.y + w1.z * b1.z + w1.w * b1.w;
        }
        s_b[tid] = a0 + a1;
    }
    __syncthreads();
    compute_Wv<false>(Wg, s_b, Wv, tid);     // Wv = Wv(v0)
    __syncthreads();

    // ======================= iteration 1 =======================
    route_pass(u_s, Wv, S_s, c, l16);
    __syncthreads();
    contract_s_full(Wg, S_s, s_b, tid);
    __syncthreads();
    compute_Wv<true>(Wg, s_b, Wv, tid);      // Wv += Wv(v1)
    __syncthreads();

    // ======================= iteration 2 =======================
    route_pass(u_s, Wv, S_s, c, l16);
    __syncthreads();
    contract_s_full(Wg, S_s, s_b, tid);
    __syncthreads();

    // out = squash(s2), squash scale recomputed per thread (broadcast reads)
    if (tid < 160) {
        const int o = tid >> 4;
        const float* srow = s_b + o * 16;
        float sn = 0.f;
#pragma unroll
        for (int p = 0; p < 16; ++p) { float t = srow[p]; sn += t * t; }
        const float sc = __fdividef(__fsqrt_rn(sn), 1.f + sn);
        outg[b * 160 + tid] = s_b[tid] * sc;
    }
}

extern "C" void kernel_launch(void* const* d_in, const int* in_sizes, int n_in,
                              void* d_out, int out_size)
{
    const float* x = (const float*)d_in[0];
    const float* W = (const float*)d_in[1];
    if (n_in >= 2 && in_sizes[0] < in_sizes[1]) {
        const float* t = x; x = W; W = t;
    }
    (void)out_size;

    cudaFuncSetAttribute(caps_routing_kernel,
                         cudaFuncAttributeMaxDynamicSharedMemorySize, SMEM_BYTES);
    caps_routing_kernel<<<B_SZ, BDIM, SMEM_BYTES>>>(x, W, (float*)d_out);
}

// round 3
// speedup vs baseline: 2.9815x; 2.0363x over previous
#include <cuda_runtime.h>
#include <math.h>

#define B_SZ   128
#define C_SZ   32
#define HW_SZ  144
#define Q_SZ   8
#define O_SZ   10
#define P_SZ   16
#define BDIM   512

#define U_STRIDE 1152            // plain [c][144][8]; no two c's share a warp now

// SMEM layout (floats)
#define U_OFF   0
#define U_SIZE  (32 * U_STRIDE)            // 36864
#define WV_OFF  U_SIZE                      // Wv  [32][10][8] = 2560 (accumulated)
#define S_OFF   (WV_OFF + 2560)             // S_s [32][10][8] = 2560 (iter0: [32][8])
#define SB_OFF  (S_OFF + 2560)              // s_b [10][16] = 160
#define SMEM_FLOATS (SB_OFF + 160)
#define SMEM_BYTES  (SMEM_FLOATS * 4)

// ---------------------------------------------------------------------------
// One c of a routing pass. Warp covers ONE c: lanes 0-15 handle o 0-4 over the
// 16 spatial lanes, lanes 16-31 handle o 5-9 over the same 16 spatial lanes.
// Wv slice (40 floats) lives in registers; accumulator is Sp[40].
// ---------------------------------------------------------------------------
__device__ __forceinline__ void route_c(const float* __restrict__ u_s,
                                        const float* __restrict__ Wv,
                                        float* __restrict__ S_s,
                                        int c, int l16, int half)
{
    // hoist this lane's 5-o Wv slice into registers
    const float4* wvp = reinterpret_cast<const float4*>(Wv + c * 80 + half * 40);
    float4 wv[10];
#pragma unroll
    for (int z = 0; z < 10; ++z) wv[z] = wvp[z];

    float Sp[40];
#pragma unroll
    for (int z = 0; z < 40; ++z) Sp[z] = 0.f;

    const float* ubase = u_s + c * U_STRIDE;

#pragma unroll
    for (int j = 0; j < 9; ++j) {
        const float4* up =
            reinterpret_cast<const float4*>(ubase + (j * 16 + l16) * Q_SZ);
        const float4 u0 = up[0];
        const float4 u1 = up[1];

        float bb[5];
#pragma unroll
        for (int o = 0; o < 5; ++o) {
            float4 w0 = wv[o * 2];
            float4 w1 = wv[o * 2 + 1];
            bb[o] = u0.x * w0.x + u0.y * w0.y + u0.z * w0.z + u0.w * w0.w
                  + u1.x * w1.x + u1.y * w1.y + u1.z * w1.z + u1.w * w1.w;
        }

        // softmax over all 10 o's: combine with partner lane (l ^ 16)
        float m = bb[0];
#pragma unroll
        for (int o = 1; o < 5; ++o) m = fmaxf(m, bb[o]);
        m = fmaxf(m, __shfl_xor_sync(0xffffffffu, m, 16));

        float ssum = 0.f;
#pragma unroll
        for (int o = 0; o < 5; ++o) { bb[o] = __expf(bb[o] - m); ssum += bb[o]; }
        ssum += __shfl_xor_sync(0xffffffffu, ssum, 16);
        const float r = __fdividef(1.f, ssum);

#pragma unroll
        for (int o = 0; o < 5; ++o) {
            const float ce = bb[o] * r;
            Sp[o * 8 + 0] += ce * u0.x;
            Sp[o * 8 + 1] += ce * u0.y;
            Sp[o * 8 + 2] += ce * u0.z;
            Sp[o * 8 + 3] += ce * u0.w;
            Sp[o * 8 + 4] += ce * u1.x;
            Sp[o * 8 + 5] += ce * u1.y;
            Sp[o * 8 + 6] += ce * u1.z;
            Sp[o * 8 + 7] += ce * u1.w;
        }
    }

    // split-butterfly reduction of 40 values over the 16 spatial lanes
    int base = 0;
    {
        const bool up = (l16 & 1);
#pragma unroll
        for (int z = 0; z < 20; ++z) {
            float keep = up ? Sp[20 + z] : Sp[z];
            float give = up ? Sp[z] : Sp[20 + z];
            Sp[z] = keep + __shfl_xor_sync(0xffffffffu, give, 1);
        }
        if (up) base += 20;
    }
    {
        const bool up = (l16 & 2);
#pragma unroll
        for (int z = 0; z < 10; ++z) {
            float keep = up ? Sp[10 + z] : Sp[z];
            float give = up ? Sp[z] : Sp[10 + z];
            Sp[z] = keep + __shfl_xor_sync(0xffffffffu, give, 2);
        }
        if (up) base += 10;
    }
    {
        const bool up = (l16 & 4);
#pragma unroll
        for (int z = 0; z < 5; ++z) {
            float keep = up ? Sp[5 + z] : Sp[z];
            float give = up ? Sp[z] : Sp[5 + z];
            Sp[z] = keep + __shfl_xor_sync(0xffffffffu, give, 4);
        }
        if (up) base += 5;
    }
#pragma unroll
    for (int z = 0; z < 5; ++z)
        Sp[z] += __shfl_xor_sync(0xffffffffu, Sp[z], 8);

    if ((l16 & 8) == 0) {
        float* dst = S_s + c * 80 + half * 40 + base;
#pragma unroll
        for (int z = 0; z < 5; ++z) dst[z] = Sp[z];
    }
}

// s[o][p] = sum_{c,q} W[c,o,p,q] * S_s[c][o][q]   (threads 0..159)
__device__ __forceinline__ void contract_s_full(const float* __restrict__ Wg,
                                                const float* __restrict__ S_s,
                                                float* __restrict__ s_b, int tid)
{
    if (tid < 160) {
        const int o = tid >> 4, p = tid & 15;
        float a0 = 0.f, a1 = 0.f, a2 = 0.f, a3 = 0.f;
#pragma unroll 4
        for (int cc = 0; cc < 32; ++cc) {
            const float4* wp =
                reinterpret_cast<const float4*>(Wg + cc * 1280 + o * 128 + p * 8);
            const float4* sp = reinterpret_cast<const float4*>(S_s + cc * 80 + o * 8);
            float4 w0 = wp[0], w1 = wp[1], b0 = sp[0], b1 = sp[1];
            a0 += w0.x * b0.x + w0.y * b0.y;
            a1 += w0.z * b0.z + w0.w * b0.w;
            a2 += w1.x * b1.x + w1.y * b1.y;
            a3 += w1.z * b1.z + w1.w * b1.w;
        }
        s_b[tid] = (a0 + a1) + (a2 + a3);
    }
}

// Wv[c][o][q] (+)= sum_p W[c,o,p,q] * squash(s)[o][p]   (threads 0..319)
template <bool ACC>
__device__ __forceinline__ void compute_Wv(const float* __restrict__ Wg,
                                           const float* __restrict__ s_b,
                                           float* __restrict__ Wv, int tid)
{
    if (tid < 320) {
        const int cc = tid / 10;
        const int o  = tid - cc * 10;
        const float* srow = s_b + o * 16;
        float sv[16];
        float sn = 0.f;
#pragma unroll
        for (int p = 0; p < 16; ++p) { sv[p] = srow[p]; sn += sv[p] * sv[p]; }
        const float sc = __fdividef(__fsqrt_rn(sn), 1.f + sn);

        const float* wrow = Wg + cc * 1280 + o * 128;
        float acc[8];
#pragma unroll
        for (int q = 0; q < 8; ++q) acc[q] = 0.f;
#pragma unroll
        for (int p = 0; p < 16; ++p) {
            const float vp = sv[p] * sc;
            const float4* wp = reinterpret_cast<const float4*>(wrow + p * 8);
            float4 w0 = wp[0], w1 = wp[1];
            acc[0] += w0.x * vp; acc[1] += w0.y * vp;
            acc[2] += w0.z * vp; acc[3] += w0.w * vp;
            acc[4] += w1.x * vp; acc[5] += w1.y * vp;
            acc[6] += w1.z * vp; acc[7] += w1.w * vp;
        }
        float4* dst = reinterpret_cast<float4*>(Wv + cc * 80 + o * 8);
        if (ACC) {
            float4 o0 = dst[0], o1 = dst[1];
            dst[0] = make_float4(o0.x + acc[0], o0.y + acc[1], o0.z + acc[2], o0.w + acc[3]);
            dst[1] = make_float4(o1.x + acc[4], o1.y + acc[5], o1.z + acc[6], o1.w + acc[7]);
        } else {
            dst[0] = make_float4(acc[0], acc[1], acc[2], acc[3]);
            dst[1] = make_float4(acc[4], acc[5], acc[6], acc[7]);
        }
    }
}

__global__ __launch_bounds__(BDIM, 1)
void caps_routing_kernel(const float* __restrict__ xg,
                         const float* __restrict__ Wg,
                         float* __restrict__ outg)
{
    extern __shared__ float sm[];
    float* u_s = sm + U_OFF;
    float* Wv  = sm + WV_OFF;
    float* S_s = sm + S_OFF;
    float* s_b = sm + SB_OFF;

    const int b   = blockIdx.x;
    const int tid = threadIdx.x;

    // ---- load x[b]: layout [c][144][8] identical to gmem ----
    {
        const float4* src = reinterpret_cast<const float4*>(xg + (size_t)b * 36864);
        float4* dst = reinterpret_cast<float4*>(u_s);
#pragma unroll
        for (int k = 0; k < 18; ++k) dst[tid + k * BDIM] = src[tid + k * BDIM];
    }
    __syncthreads();

    const int w    = tid >> 5;      // warp id 0..15
    const int lane = tid & 31;
    const int l16  = lane & 15;
    const int half = lane >> 4;     // o-half: 0 -> o 0-4, 1 -> o 5-9

    // ======================= iteration 0 (c_ij = 1/10) =======================
#pragma unroll
    for (int ci = 0; ci < 2; ++ci) {
        const int c = w + 16 * ci;
        float S0[8];
#pragma unroll
        for (int q = 0; q < 8; ++q) S0[q] = 0.f;
        const float* ubase = u_s + c * U_STRIDE;
#pragma unroll
        for (int j = 0; j < 5; ++j) {
            const int pt = j * 32 + lane;
            if (pt < 144) {
                const float4* up =
                    reinterpret_cast<const float4*>(ubase + pt * Q_SZ);
                float4 a = up[0], bq = up[1];
                S0[0] += a.x;  S0[1] += a.y;  S0[2] += a.z;  S0[3] += a.w;
                S0[4] += bq.x; S0[5] += bq.y; S0[6] += bq.z; S0[7] += bq.w;
            }
        }
        // split-butterfly over 32 lanes
        int base = 0;
        {
            const bool up = (lane & 1);
#pragma unroll
            for (int z = 0; z < 4; ++z) {
                float keep = up ? S0[4 + z] : S0[z];
                float give = up ? S0[z] : S0[4 + z];
                S0[z] = keep + __shfl_xor_sync(0xffffffffu, give, 1);
            }
            if (up) base += 4;
        }
        {
            const bool up = (lane & 2);
#pragma unroll
            for (int z = 0; z < 2; ++z) {
                float keep = up ? S0[2 + z] : S0[z];
                float give = up ? S0[z] : S0[2 + z];
                S0[z] = keep + __shfl_xor_sync(0xffffffffu, give, 2);
            }
            if (up) base += 2;
        }
        {
            const bool up = (lane & 4);
            float keep = up ? S0[1] : S0[0];
            float give = up ? S0[0] : S0[1];
            S0[0] = keep + __shfl_xor_sync(0xffffffffu, give, 4);
            if (up) base += 1;
        }
        S0[0] += __shfl_xor_sync(0xffffffffu, S0[0], 8);
        S0[0] += __shfl_xor_sync(0xffffffffu, S0[0], 16);
        if (lane < 8) S_s[c * 8 + base] = S0[0] * 0.1f;
    }
    __syncthreads();

    // s0[o][p] = sum_{c,q} W[c,o,p,q] * S_s[c][q]
    if (tid < 160) {
        const int o = tid >> 4, p = tid & 15;
        float a0 = 0.f, a1 = 0.f;
#pragma unroll 4
        for (int cc = 0; cc < 32; ++cc) {
            const float4* wp =
                reinterpret_cast<const float4*>(Wg + cc * 1280 + o * 128 + p * 8);
            const float4* sp = reinterpret_cast<const float4*>(S_s + cc * 8);
            float4 w0 = wp[0], w1 = wp[1], b0 = sp[0], b1 = sp[1];
            a0 += w0.x * b0.x + w0.y * b0.y + w0.z * b0.z + w0.w * b0.w;
            a1 += w1.x * b1.x + w1.y * b1.y + w1.z * b1.z + w1.w * b1.w;
        }
        s_b[tid] = a0 + a1;
    }
    __syncthreads();
    compute_Wv<false>(Wg, s_b, Wv, tid);      // Wv = Wv(v0)
    __syncthreads();

    // ======================= iteration 1 =======================
    route_c(u_s, Wv, S_s, w, l16, half);
    route_c(u_s, Wv, S_s, w + 16, l16, half);
    __syncthreads();
    contract_s_full(Wg, S_s, s_b, tid);
    __syncthreads();
    compute_Wv<true>(Wg, s_b, Wv, tid);       // Wv += Wv(v1)
    __syncthreads();

    // ======================= iteration 2 =======================
    route_c(u_s, Wv, S_s, w, l16, half);
    route_c(u_s, Wv, S_s, w + 16, l16, half);
    __syncthreads();
    contract_s_full(Wg, S_s, s_b, tid);
    __syncthreads();

    // out = squash(s2)
    if (tid < 160) {
        const int o = tid >> 4;
        const float* srow = s_b + o * 16;
        float sn = 0.f;
#pragma unroll
        for (int p = 0; p < 16; ++p) { float t = srow[p]; sn += t * t; }
        const float sc = __fdividef(__fsqrt_rn(sn), 1.f + sn);
        outg[b * 160 + tid] = s_b[tid] * sc;
    }
}

extern "C" void kernel_launch(void* const* d_in, const int* in_sizes, int n_in,
                              void* d_out, int out_size)
{
    const float* x = (const float*)d_in[0];
    const float* W = (const float*)d_in[1];
    if (n_in >= 2 && in_sizes[0] < in_sizes[1]) {
        const float* t = x; x = W; W = t;
    }
    (void)out_size;

    cudaFuncSetAttribute(caps_routing_kernel,
                         cudaFuncAttributeMaxDynamicSharedMemorySize, SMEM_BYTES);
    caps_routing_kernel<<<B_SZ, BDIM, SMEM_BYTES>>>(x, W, (float*)d_out);
}

// round 4
// speedup vs baseline: 3.1161x; 1.0452x over previous
#include <cuda_runtime.h>
#include <math.h>

#define B_SZ   128
#define C_SZ   32
#define HW_SZ  144
#define Q_SZ   8
#define O_SZ   10
#define P_SZ   16
#define BDIM   512

#define U_STRIDE 1152

// SMEM layout (floats)
#define U_OFF   0
#define U_SIZE  (32 * U_STRIDE)             // 36864
#define WV_OFF  U_SIZE                       // Wv   [32][10][8] = 2560 (accumulated)
#define S_OFF   (WV_OFF + 2560)              // S_s  [32][10][8] = 2560 (iter0: [32][8])
#define SB_OFF  (S_OFF + 2560)               // s_b  [10][16]    = 160
#define PART_OFF (SB_OFF + 160)              // part [2][160]    = 320
#define SMEM_FLOATS (PART_OFF + 320)
#define SMEM_BYTES  (SMEM_FLOATS * 4)

typedef unsigned long long u64p;             // packed f32x2

__device__ __forceinline__ u64p pk2(float lo, float hi) {
    u64p r; asm("mov.b64 %0, {%1, %2};" : "=l"(r) : "f"(lo), "f"(hi)); return r;
}
__device__ __forceinline__ void upk2(u64p v, float& lo, float& hi) {
    asm("mov.b64 {%0, %1}, %2;" : "=f"(lo), "=f"(hi) : "l"(v));
}
#define FMA2(d, a, b, c) asm("fma.rn.f32x2 %0, %1, %2, %3;" : "=l"(d) : "l"(a), "l"(b), "l"(c))
#define MUL2(d, a, b)    asm("mul.rn.f32x2 %0, %1, %2;"      : "=l"(d) : "l"(a), "l"(b))

// ---------------------------------------------------------------------------
// Routing pass for one c. Lanes 0-15: o 0-4, lanes 16-31: o 5-9, 16 spatial
// lanes x 9 steps. Wv slice and Sp accumulators in packed f32x2 registers.
// ---------------------------------------------------------------------------
__device__ __forceinline__ void route_c(const float* __restrict__ u_s,
                                        const float* __restrict__ Wv,
                                        float* __restrict__ S_s,
                                        int c, int l16, int half)
{
    const ulonglong2* wvp =
        reinterpret_cast<const ulonglong2*>(Wv + c * 80 + half * 40);
    u64p wv[20];
#pragma unroll
    for (int z = 0; z < 10; ++z) { ulonglong2 t = wvp[z]; wv[2*z] = t.x; wv[2*z+1] = t.y; }

    u64p Sp[20];
#pragma unroll
    for (int z = 0; z < 20; ++z) Sp[z] = 0ULL;

    const float* ubase = u_s + c * U_STRIDE;

#pragma unroll
    for (int j = 0; j < 9; ++j) {
        const ulonglong2* up =
            reinterpret_cast<const ulonglong2*>(ubase + (j * 16 + l16) * Q_SZ);
        const ulonglong2 ua = up[0];
        const ulonglong2 ub = up[1];
        const u64p uq0 = ua.x, uq1 = ua.y, uq2 = ub.x, uq3 = ub.y;

        // logits for my 5 o's (packed dot)
        float bb[5];
#pragma unroll
        for (int o = 0; o < 5; ++o) {
            u64p t;
            MUL2(t, uq0, wv[4*o]);
            FMA2(t, uq1, wv[4*o+1], t);
            FMA2(t, uq2, wv[4*o+2], t);
            FMA2(t, uq3, wv[4*o+3], t);
            float lo, hi; upk2(t, lo, hi);
            bb[o] = lo + hi;
        }

        // local-max softmax: exchange (m, sum) AFTER exps; combine exactly.
        const float m = fmaxf(fmaxf(fmaxf(bb[0], bb[1]), fmaxf(bb[2], bb[3])), bb[4]);
        const float mb = __shfl_xor_sync(0xffffffffu, m, 16);
        float ex[5];
#pragma unroll
        for (int o = 0; o < 5; ++o) ex[o] = __expf(bb[o] - m);
        const float sa = ((ex[0] + ex[1]) + (ex[2] + ex[3])) + ex[4];
        const float sb = __shfl_xor_sync(0xffffffffu, sa, 16);
        const float M  = fmaxf(m, mb);
        const float da = __expf(m - M);
        const float db = __expf(mb - M);
        const float r  = __fdividef(da, sa * da + sb * db);

#pragma unroll
        for (int o = 0; o < 5; ++o) {
            const float ce = ex[o] * r;
            const u64p cep = pk2(ce, ce);
            FMA2(Sp[4*o+0], cep, uq0, Sp[4*o+0]);
            FMA2(Sp[4*o+1], cep, uq1, Sp[4*o+1]);
            FMA2(Sp[4*o+2], cep, uq2, Sp[4*o+2]);
            FMA2(Sp[4*o+3], cep, uq3, Sp[4*o+3]);
        }
    }

    // unpack and split-butterfly reduce 40 values over the 16 spatial lanes
    float v[40];
#pragma unroll
    for (int z = 0; z < 20; ++z) upk2(Sp[z], v[2*z], v[2*z+1]);

    int base = 0;
    {
        const bool up = (l16 & 1);
#pragma unroll
        for (int z = 0; z < 20; ++z) {
            float keep = up ? v[20 + z] : v[z];
            float give = up ? v[z] : v[20 + z];
            v[z] = keep + __shfl_xor_sync(0xffffffffu, give, 1);
        }
        if (up) base += 20;
    }
    {
        const bool up = (l16 & 2);
#pragma unroll
        for (int z = 0; z < 10; ++z) {
            float keep = up ? v[10 + z] : v[z];
            float give = up ? v[z] : v[10 + z];
            v[z] = keep + __shfl_xor_sync(0xffffffffu, give, 2);
        }
        if (up) base += 10;
    }
    {
        const bool up = (l16 & 4);
#pragma unroll
        for (int z = 0; z < 5; ++z) {
            float keep = up ? v[5 + z] : v[z];
            float give = up ? v[z] : v[5 + z];
            v[z] = keep + __shfl_xor_sync(0xffffffffu, give, 4);
        }
        if (up) base += 5;
    }
#pragma unroll
    for (int z = 0; z < 5; ++z)
        v[z] += __shfl_xor_sync(0xffffffffu, v[z], 8);

    if ((l16 & 8) == 0) {
        float* dst = S_s + c * 80 + half * 40 + base;
#pragma unroll
        for (int z = 0; z < 5; ++z) dst[z] = v[z];
    }
}

// partial contract: 320 threads, h = tid/160 handles c in [16h, 16h+16)
// PER_O: S_s is [c][o][8] (routing iters) vs [c][8] (iter0).
template <bool PER_O>
__device__ __forceinline__ void contract_partial(const float* __restrict__ Wg,
                                                 const float* __restrict__ S_s,
                                                 float* __restrict__ part, int tid)
{
    if (tid < 320) {
        const int h   = (tid >= 160);
        const int idx = tid - h * 160;
        const int o = idx >> 4, p = idx & 15;
        float a0 = 0.f, a1 = 0.f, a2 = 0.f, a3 = 0.f;
        const int c0 = h * 16;
#pragma unroll
        for (int k = 0; k < 16; ++k) {
            const int cc = c0 + k;
            const float4* wp =
                reinterpret_cast<const float4*>(Wg + cc * 1280 + o * 128 + p * 8);
            const float4* sp = reinterpret_cast<const float4*>(
                S_s + (PER_O ? (cc * 80 + o * 8) : (cc * 8)));
            float4 w0 = wp[0], w1 = wp[1], b0 = sp[0], b1 = sp[1];
            a0 += w0.x * b0.x + w0.y * b0.y;
            a1 += w0.z * b0.z + w0.w * b0.w;
            a2 += w1.x * b1.x + w1.y * b1.y;
            a3 += w1.z * b1.z + w1.w * b1.w;
        }
        part[h * 160 + idx] = (a0 + a1) + (a2 + a3);
    }
}

// Wv[c][o][q] (+)= sum_p W[c,o,p,q] * squash(s)[o][p]   (threads 0..319)
template <bool ACC>
__device__ __forceinline__ void compute_Wv(const float* __restrict__ Wg,
                                           const float* __restrict__ s_b,
                                           float* __restrict__ Wv, int tid)
{
    if (tid < 320) {
        const int cc = tid / 10;
        const int o  = tid - cc * 10;
        const float* srow = s_b + o * 16;
        float sv[16];
        float sn = 0.f;
#pragma unroll
        for (int p = 0; p < 16; ++p) { sv[p] = srow[p]; sn += sv[p] * sv[p]; }
        const float sc = __fdividef(__fsqrt_rn(sn), 1.f + sn);

        const float* wrow = Wg + cc * 1280 + o * 128;
        float acc[8];
#pragma unroll
        for (int q = 0; q < 8; ++q) acc[q] = 0.f;
#pragma unroll
        for (int p = 0; p < 16; ++p) {
            const float vp = sv[p] * sc;
            const float4* wp = reinterpret_cast<const float4*>(wrow + p * 8);
            float4 w0 = wp[0], w1 = wp[1];
            acc[0] += w0.x * vp; acc[1] += w0.y * vp;
            acc[2] += w0.z * vp; acc[3] += w0.w * vp;
            acc[4] += w1.x * vp; acc[5] += w1.y * vp;
            acc[6] += w1.z * vp; acc[7] += w1.w * vp;
        }
        float4* dst = reinterpret_cast<float4*>(Wv + cc * 80 + o * 8);
        if (ACC) {
            float4 o0 = dst[0], o1 = dst[1];
            dst[0] = make_float4(o0.x + acc[0], o0.y + acc[1], o0.z + acc[2], o0.w + acc[3]);
            dst[1] = make_float4(o1.x + acc[4], o1.y + acc[5], o1.z + acc[6], o1.w + acc[7]);
        } else {
            dst[0] = make_float4(acc[0], acc[1], acc[2], acc[3]);
            dst[1] = make_float4(acc[4], acc[5], acc[6], acc[7]);
        }
    }
}

__global__ __launch_bounds__(BDIM, 1)
void caps_routing_kernel(const float* __restrict__ xg,
                         const float* __restrict__ Wg,
                         float* __restrict__ outg)
{
    extern __shared__ float sm[];
    float* u_s  = sm + U_OFF;
    float* Wv   = sm + WV_OFF;
    float* S_s  = sm + S_OFF;
    float* s_b  = sm + SB_OFF;
    float* part = sm + PART_OFF;

    const int b    = blockIdx.x;
    const int tid  = threadIdx.x;
    const int w    = tid >> 5;
    const int lane = tid & 31;
    const int l16  = lane & 15;
    const int half = lane >> 4;

    // ---- fused load + iteration 0: warp w owns c = w and c = w+16.
    // Each lane loads 9 float4 per c (coalesced) and accumulates their sum.
    // float4 index parity == lane parity, so even lanes hold q0-3 partials
    // and odd lanes hold q4-7 partials. Butterfly over masks 2,4,8,16.
#pragma unroll
    for (int ci = 0; ci < 2; ++ci) {
        const int c = w + 16 * ci;
        const float4* src =
            reinterpret_cast<const float4*>(xg + (size_t)b * 36864 + c * 1152);
        float4* dst = reinterpret_cast<float4*>(u_s + c * U_STRIDE);
        float4 acc = make_float4(0.f, 0.f, 0.f, 0.f);
#pragma unroll
        for (int k = 0; k < 9; ++k) {
            float4 t = src[lane + 32 * k];
            dst[lane + 32 * k] = t;
            acc.x += t.x; acc.y += t.y; acc.z += t.z; acc.w += t.w;
        }
#pragma unroll
        for (int msk = 2; msk <= 16; msk <<= 1) {
            acc.x += __shfl_xor_sync(0xffffffffu, acc.x, msk);
            acc.y += __shfl_xor_sync(0xffffffffu, acc.y, msk);
            acc.z += __shfl_xor_sync(0xffffffffu, acc.z, msk);
            acc.w += __shfl_xor_sync(0xffffffffu, acc.w, msk);
        }
        if (lane < 2) {   // lane0 -> q0-3, lane1 -> q4-7
            float4* so = reinterpret_cast<float4*>(S_s + c * 8 + lane * 4);
            so[0] = make_float4(acc.x * 0.1f, acc.y * 0.1f, acc.z * 0.1f, acc.w * 0.1f);
        }
    }
    __syncthreads();

    // ---- iteration 0 contract + Wv(v0)
    contract_partial<false>(Wg, S_s, part, tid);
    __syncthreads();
    if (tid < 160) s_b[tid] = part[tid] + part[160 + tid];
    __syncthreads();
    compute_Wv<false>(Wg, s_b, Wv, tid);
    __syncthreads();

    // ---- iteration 1
    route_c(u_s, Wv, S_s, w, l16, half);
    route_c(u_s, Wv, S_s, w + 16, l16, half);
    __syncthreads();
    contract_partial<true>(Wg, S_s, part, tid);
    __syncthreads();
    if (tid < 160) s_b[tid] = part[tid] + part[160 + tid];
    __syncthreads();
    compute_Wv<true>(Wg, s_b, Wv, tid);
    __syncthreads();

    // ---- iteration 2
    route_c(u_s, Wv, S_s, w, l16, half);
    route_c(u_s, Wv, S_s, w + 16, l16, half);
    __syncthreads();
    contract_partial<true>(Wg, S_s, part, tid);
    __syncthreads();
    if (tid < 160) s_b[tid] = part[tid] + part[160 + tid];
    __syncthreads();

    // out = squash(s2)
    if (tid < 160) {
        const int o = tid >> 4;
        const float* srow = s_b + o * 16;
        float sn = 0.f;
#pragma unroll
        for (int p = 0; p < 16; ++p) { float t = srow[p]; sn += t * t; }
        const float sc = __fdividef(__fsqrt_rn(sn), 1.f + sn);
        outg[b * 160 + tid] = s_b[tid] * sc;
    }
}

extern "C" void kernel_launch(void* const* d_in, const int* in_sizes, int n_in,
                              void* d_out, int out_size)
{
    const float* x = (const float*)d_in[0];
    const float* W = (const float*)d_in[1];
    if (n_in >= 2 && in_sizes[0] < in_sizes[1]) {
        const float* t = x; x = W; W = t;
    }
    (void)out_size;

    cudaFuncSetAttribute(caps_routing_kernel,
                         cudaFuncAttributeMaxDynamicSharedMemorySize, SMEM_BYTES);
    caps_routing_kernel<<<B_SZ, BDIM, SMEM_BYTES>>>(x, W, (float*)d_out);
}

// round 5
// speedup vs baseline: 3.3111x; 1.0626x over previous
#include <cuda_runtime.h>
#include <math.h>

#define B_SZ   128
#define C_SZ   32
#define HW_SZ  144
#define Q_SZ   8
#define O_SZ   10
#define P_SZ   16
#define BDIM   512

#define U_STRIDE 1152

// SMEM layout (floats)
#define U_OFF   0
#define U_SIZE  (32 * U_STRIDE)             // 36864
#define WV_OFF  U_SIZE                       // Wv   [32][10][8] = 2560 (accumulated, log2e-scaled)
#define S_OFF   (WV_OFF + 2560)              // S_s  [32][10][8] = 2560 (iter0: [32][8])
#define SB_OFF  (S_OFF + 2560)               // s_b  [10][16]    = 160
#define PART_OFF (SB_OFF + 160)              // part [2][160]    = 320
#define SMEM_FLOATS (PART_OFF + 320)
#define SMEM_BYTES  (SMEM_FLOATS * 4)

#define LOG2E 1.4426950408889634f

typedef unsigned long long u64p;             // packed f32x2

__device__ __forceinline__ u64p pk2(float lo, float hi) {
    u64p r; asm("mov.b64 %0, {%1, %2};" : "=l"(r) : "f"(lo), "f"(hi)); return r;
}
__device__ __forceinline__ void upk2(u64p v, float& lo, float& hi) {
    asm("mov.b64 {%0, %1}, %2;" : "=f"(lo), "=f"(hi) : "l"(v));
}
__device__ __forceinline__ float ex2f(float x) {
    float y; asm("ex2.approx.ftz.f32 %0, %1;" : "=f"(y) : "f"(x)); return y;
}
#define FMA2(d, a, b, c) asm("fma.rn.f32x2 %0, %1, %2, %3;" : "=l"(d) : "l"(a), "l"(b), "l"(c))
#define MUL2(d, a, b)    asm("mul.rn.f32x2 %0, %1, %2;"      : "=l"(d) : "l"(a), "l"(b))

// ---------------------------------------------------------------------------
// Routing pass for one c. Lanes 0-15: o 0-4, lanes 16-31: o 5-9, 16 spatial
// lanes x 9 steps. Wv slice (log2e-scaled) and Sp accumulators in f32x2 regs.
// j-loop partially unrolled (3) to bound register pressure (no spills).
// ---------------------------------------------------------------------------
__device__ __forceinline__ void route_c(const float* __restrict__ u_s,
                                        const float* __restrict__ Wv,
                                        float* __restrict__ S_s,
                                        int c, int l16, int half)
{
    const ulonglong2* wvp =
        reinterpret_cast<const ulonglong2*>(Wv + c * 80 + half * 40);
    u64p wv[20];
#pragma unroll
    for (int z = 0; z < 10; ++z) { ulonglong2 t = wvp[z]; wv[2*z] = t.x; wv[2*z+1] = t.y; }

    u64p Sp[20];
#pragma unroll
    for (int z = 0; z < 20; ++z) Sp[z] = 0ULL;

    const float* ubase = u_s + c * U_STRIDE;

#pragma unroll 3
    for (int j = 0; j < 9; ++j) {
        const ulonglong2* up =
            reinterpret_cast<const ulonglong2*>(ubase + (j * 16 + l16) * Q_SZ);
        const ulonglong2 ua = up[0];
        const ulonglong2 ub = up[1];
        const u64p uq0 = ua.x, uq1 = ua.y, uq2 = ub.x, uq3 = ub.y;

        // logits (already in log2 domain: Wv pre-scaled by log2e)
        float bb[5];
#pragma unroll
        for (int o = 0; o < 5; ++o) {
            u64p t;
            MUL2(t, uq0, wv[4*o]);
            FMA2(t, uq1, wv[4*o+1], t);
            FMA2(t, uq2, wv[4*o+2], t);
            FMA2(t, uq3, wv[4*o+3], t);
            float lo, hi; upk2(t, lo, hi);
            bb[o] = lo + hi;
        }

        // local-max softmax in log2 domain; exchange (m, sum) after exps
        const float m = fmaxf(fmaxf(fmaxf(bb[0], bb[1]), fmaxf(bb[2], bb[3])), bb[4]);
        const float mb = __shfl_xor_sync(0xffffffffu, m, 16);
        float ex[5];
#pragma unroll
        for (int o = 0; o < 5; ++o) ex[o] = ex2f(bb[o] - m);
        const float sa = ((ex[0] + ex[1]) + (ex[2] + ex[3])) + ex[4];
        const float sb = __shfl_xor_sync(0xffffffffu, sa, 16);
        const float M  = fmaxf(m, mb);
        const float da = ex2f(m - M);
        const float db = ex2f(mb - M);
        const float r  = __fdividef(da, sa * da + sb * db);

#pragma unroll
        for (int o = 0; o < 5; ++o) {
            const float ce = ex[o] * r;
            const u64p cep = pk2(ce, ce);
            FMA2(Sp[4*o+0], cep, uq0, Sp[4*o+0]);
            FMA2(Sp[4*o+1], cep, uq1, Sp[4*o+1]);
            FMA2(Sp[4*o+2], cep, uq2, Sp[4*o+2]);
            FMA2(Sp[4*o+3], cep, uq3, Sp[4*o+3]);
        }
    }

    // unpack and split-butterfly reduce 40 values over the 16 spatial lanes
    float v[40];
#pragma unroll
    for (int z = 0; z < 20; ++z) upk2(Sp[z], v[2*z], v[2*z+1]);

    int base = 0;
    {
        const bool up = (l16 & 1);
#pragma unroll
        for (int z = 0; z < 20; ++z) {
            float keep = up ? v[20 + z] : v[z];
            float give = up ? v[z] : v[20 + z];
            v[z] = keep + __shfl_xor_sync(0xffffffffu, give, 1);
        }
        if (up) base += 20;
    }
    {
        const bool up = (l16 & 2);
#pragma unroll
        for (int z = 0; z < 10; ++z) {
            float keep = up ? v[10 + z] : v[z];
            float give = up ? v[z] : v[10 + z];
            v[z] = keep + __shfl_xor_sync(0xffffffffu, give, 2);
        }
        if (up) base += 10;
    }
    {
        const bool up = (l16 & 4);
#pragma unroll
        for (int z = 0; z < 5; ++z) {
            float keep = up ? v[5 + z] : v[z];
            float give = up ? v[z] : v[5 + z];
            v[z] = keep + __shfl_xor_sync(0xffffffffu, give, 4);
        }
        if (up) base += 5;
    }
#pragma unroll
    for (int z = 0; z < 5; ++z)
        v[z] += __shfl_xor_sync(0xffffffffu, v[z], 8);

    if ((l16 & 8) == 0) {
        float* dst = S_s + c * 80 + half * 40 + base;
#pragma unroll
        for (int z = 0; z < 5; ++z) dst[z] = v[z];
    }
}

// partial contract: 320 threads, h = tid/160 handles c in [16h, 16h+16)
template <bool PER_O>
__device__ __forceinline__ void contract_partial(const float* __restrict__ Wg,
                                                 const float* __restrict__ S_s,
                                                 float* __restrict__ part, int tid)
{
    if (tid < 320) {
        const int h   = (tid >= 160);
        const int idx = tid - h * 160;
        const int o = idx >> 4, p = idx & 15;
        float a0 = 0.f, a1 = 0.f, a2 = 0.f, a3 = 0.f;
        const int c0 = h * 16;
#pragma unroll
        for (int k = 0; k < 16; ++k) {
            const int cc = c0 + k;
            const float4* wp =
                reinterpret_cast<const float4*>(Wg + cc * 1280 + o * 128 + p * 8);
            const float4* sp = reinterpret_cast<const float4*>(
                S_s + (PER_O ? (cc * 80 + o * 8) : (cc * 8)));
            float4 w0 = wp[0], w1 = wp[1], b0 = sp[0], b1 = sp[1];
            a0 += w0.x * b0.x + w0.y * b0.y;
            a1 += w0.z * b0.z + w0.w * b0.w;
            a2 += w1.x * b1.x + w1.y * b1.y;
            a3 += w1.z * b1.z + w1.w * b1.w;
        }
        part[h * 160 + idx] = (a0 + a1) + (a2 + a3);
    }
}

// Wv[c][o][q] (+)= log2e * sum_p W[c,o,p,q] * squash(s)[o][p]  (threads 0..319)
template <bool ACC>
__device__ __forceinline__ void compute_Wv(const float* __restrict__ Wg,
                                           const float* __restrict__ s_b,
                                           float* __restrict__ Wv, int tid)
{
    if (tid < 320) {
        const int cc = tid / 10;
        const int o  = tid - cc * 10;
        const float* srow = s_b + o * 16;
        float sv[16];
        float sn = 0.f;
#pragma unroll
        for (int p = 0; p < 16; ++p) { sv[p] = srow[p]; sn += sv[p] * sv[p]; }
        // squash scale * log2e folded together
        const float sc = __fdividef(__fsqrt_rn(sn) * LOG2E, 1.f + sn);

        const float* wrow = Wg + cc * 1280 + o * 128;
        float acc[8];
#pragma unroll
        for (int q = 0; q < 8; ++q) acc[q] = 0.f;
#pragma unroll
        for (int p = 0; p < 16; ++p) {
            const float vp = sv[p] * sc;
            const float4* wp = reinterpret_cast<const float4*>(wrow + p * 8);
            float4 w0 = wp[0], w1 = wp[1];
            acc[0] += w0.x * vp; acc[1] += w0.y * vp;
            acc[2] += w0.z * vp; acc[3] += w0.w * vp;
            acc[4] += w1.x * vp; acc[5] += w1.y * vp;
            acc[6] += w1.z * vp; acc[7] += w1.w * vp;
        }
        float4* dst = reinterpret_cast<float4*>(Wv + cc * 80 + o * 8);
        if (ACC) {
            float4 o0 = dst[0], o1 = dst[1];
            dst[0] = make_float4(o0.x + acc[0], o0.y + acc[1], o0.z + acc[2], o0.w + acc[3]);
            dst[1] = make_float4(o1.x + acc[4], o1.y + acc[5], o1.z + acc[6], o1.w + acc[7]);
        } else {
            dst[0] = make_float4(acc[0], acc[1], acc[2], acc[3]);
            dst[1] = make_float4(acc[4], acc[5], acc[6], acc[7]);
        }
    }
}

__global__ __launch_bounds__(BDIM, 1)
void caps_routing_kernel(const float* __restrict__ xg,
                         const float* __restrict__ Wg,
                         float* __restrict__ outg)
{
    extern __shared__ float sm[];
    float* u_s  = sm + U_OFF;
    float* Wv   = sm + WV_OFF;
    float* S_s  = sm + S_OFF;
    float* s_b  = sm + SB_OFF;
    float* part = sm + PART_OFF;

    const int b    = blockIdx.x;
    const int tid  = threadIdx.x;
    const int w    = tid >> 5;
    const int lane = tid & 31;
    const int l16  = lane & 15;
    const int half = lane >> 4;

    // ---- fused load + iteration 0 partial sums
#pragma unroll
    for (int ci = 0; ci < 2; ++ci) {
        const int c = w + 16 * ci;
        const float4* src =
            reinterpret_cast<const float4*>(xg + (size_t)b * 36864 + c * 1152);
        float4* dst = reinterpret_cast<float4*>(u_s + c * U_STRIDE);
        float4 acc = make_float4(0.f, 0.f, 0.f, 0.f);
#pragma unroll
        for (int k = 0; k < 9; ++k) {
            float4 t = src[lane + 32 * k];
            dst[lane + 32 * k] = t;
            acc.x += t.x; acc.y += t.y; acc.z += t.z; acc.w += t.w;
        }
#pragma unroll
        for (int msk = 2; msk <= 16; msk <<= 1) {
            acc.x += __shfl_xor_sync(0xffffffffu, acc.x, msk);
            acc.y += __shfl_xor_sync(0xffffffffu, acc.y, msk);
            acc.z += __shfl_xor_sync(0xffffffffu, acc.z, msk);
            acc.w += __shfl_xor_sync(0xffffffffu, acc.w, msk);
        }
        if (lane < 2) {
            float4* so = reinterpret_cast<float4*>(S_s + c * 8 + lane * 4);
            so[0] = make_float4(acc.x * 0.1f, acc.y * 0.1f, acc.z * 0.1f, acc.w * 0.1f);
        }
    }
    __syncthreads();

    // ---- iteration 0 contract + Wv(v0)
    contract_partial<false>(Wg, S_s, part, tid);
    __syncthreads();
    if (tid < 160) s_b[tid] = part[tid] + part[160 + tid];
    __syncthreads();
    compute_Wv<false>(Wg, s_b, Wv, tid);
    __syncthreads();

    // ---- iteration 1
    route_c(u_s, Wv, S_s, w, l16, half);
    route_c(u_s, Wv, S_s, w + 16, l16, half);
    __syncthreads();
    contract_partial<true>(Wg, S_s, part, tid);
    __syncthreads();
    if (tid < 160) s_b[tid] = part[tid] + part[160 + tid];
    __syncthreads();
    compute_Wv<true>(Wg, s_b, Wv, tid);
    __syncthreads();

    // ---- iteration 2
    route_c(u_s, Wv, S_s, w, l16, half);
    route_c(u_s, Wv, S_s, w + 16, l16, half);
    __syncthreads();
    contract_partial<true>(Wg, S_s, part, tid);
    __syncthreads();
    if (tid < 160) s_b[tid] = part[tid] + part[160 + tid];
    __syncthreads();

    // out = squash(s2)
    if (tid < 160) {
        const int o = tid >> 4;
        const float* srow = s_b + o * 16;
        float sn = 0.f;
#pragma unroll
        for (int p = 0; p < 16; ++p) { float t = srow[p]; sn += t * t; }
        const float sc = __fdividef(__fsqrt_rn(sn), 1.f + sn);
        outg[b * 160 + tid] = s_b[tid] * sc;
    }
}

extern "C" void kernel_launch(void* const* d_in, const int* in_sizes, int n_in,
                              void* d_out, int out_size)
{
    const float* x = (const float*)d_in[0];
    const float* W = (const float*)d_in[1];
    if (n_in >= 2 && in_sizes[0] < in_sizes[1]) {
        const float* t = x; x = W; W = t;
    }
    (void)out_size;

    cudaFuncSetAttribute(caps_routing_kernel,
                         cudaFuncAttributeMaxDynamicSharedMemorySize, SMEM_BYTES);
    caps_routing_kernel<<<B_SZ, BDIM, SMEM_BYTES>>>(x, W, (float*)d_out);
}